// round 17
// baseline (speedup 1.0000x reference)
#include <cuda_runtime.h>
#include <cuda_fp16.h>
#include <cstdint>

#define IN_CH 50
#define OUT_CH 121
#define YPITCH 128
#define MAX_N 100000

// Node-level Y = X @ W1 stored as fp16 (25.6MB -> L2-resident)
__device__ __align__(16) __half g_y[MAX_N * YPITCH];

// ---------------------------------------------------------------------------
// helpers
// ---------------------------------------------------------------------------
__device__ __forceinline__ uint32_t smem_u32(const void* p) {
    uint32_t a;
    asm("{ .reg .u64 t; cvta.to.shared.u64 t, %1; cvt.u32.u64 %0, t; }" : "=r"(a) : "l"(p));
    return a;
}

#define LDSM_X4(r0, r1, r2, r3, a) \
    asm volatile("ldmatrix.sync.aligned.m8n8.x4.shared.b16 {%0,%1,%2,%3}, [%4];" \
                 : "=r"(r0), "=r"(r1), "=r"(r2), "=r"(r3) : "r"(a))

// rowgroup barrier: 4 warps (128 threads), ids 1..4
#define BAR_RG(id) asm volatile("bar.sync %0, 128;" :: "r"(id) : "memory")

__device__ __forceinline__ void mma16816(float* c, const uint32_t* a, uint32_t b0, uint32_t b1) {
    asm volatile(
        "mma.sync.aligned.m16n8k16.row.col.f32.f16.f16.f32 "
        "{%0,%1,%2,%3}, {%4,%5,%6,%7}, {%8,%9}, {%0,%1,%2,%3};"
        : "+f"(c[0]), "+f"(c[1]), "+f"(c[2]), "+f"(c[3])
        : "r"(a[0]), "r"(a[1]), "r"(a[2]), "r"(a[3]), "r"(b0), "r"(b1));
}

// FFMA2 helpers (node kernel)
__device__ __forceinline__ void fma2(unsigned long long &d, unsigned long long a, unsigned long long b) {
    asm("fma.rn.f32x2 %0, %1, %2, %0;" : "+l"(d) : "l"(a), "l"(b));
}
__device__ __forceinline__ unsigned long long pack2(float x, float y) {
    unsigned long long r; asm("mov.b64 %0, {%1, %2};" : "=l"(r) : "f"(x), "f"(y)); return r;
}
__device__ __forceinline__ float2 unpack2(unsigned long long v) {
    float2 r; asm("mov.b64 {%0, %1}, %2;" : "=f"(r.x), "=f"(r.y) : "l"(v)); return r;
}

// ============================================================================
// Kernel A: Y[N,128] = X[N,50] @ W1[50,121] -> fp16, zero-padded cols
// ============================================================================
__global__ void __launch_bounds__(256, 1) node_gemm(const float* __restrict__ x,
                                                    const float* __restrict__ W1,
                                                    int N) {
    extern __shared__ float sm[];
    float* Xs  = sm;
    float* W1s = Xs + IN_CH * 132;

    int tid = threadIdx.x;
    int e0 = blockIdx.x * 128;

    for (int i = tid; i < 128 * IN_CH; i += 256) {
        int m = i / IN_CH, k = i - m * IN_CH;
        int node = e0 + m;
        Xs[k * 132 + m] = (node < N) ? x[(long)node * IN_CH + k] : 0.f;
    }
    for (int i = tid; i < IN_CH * 128; i += 256) {
        int k = i >> 7, n = i & 127;
        W1s[i] = (n < OUT_CH) ? W1[k * OUT_CH + n] : 0.f;
    }
    __syncthreads();

    int tx = tid & 15, ty = tid >> 4;
    unsigned long long acc[8][4];
#pragma unroll
    for (int i = 0; i < 8; i++)
#pragma unroll
        for (int j = 0; j < 4; j++) acc[i][j] = 0ULL;

    const float* ap  = Xs + ty * 8;
    const float* bp0 = W1s + tx * 4;
    const float* bp1 = W1s + 64 + tx * 4;

#pragma unroll 5
    for (int k = 0; k < IN_CH; k++) {
        float4 a0 = *(const float4*)(ap + k * 132);
        float4 a1 = *(const float4*)(ap + k * 132 + 4);
        float4 b0 = *(const float4*)(bp0 + k * 128);
        float4 b1 = *(const float4*)(bp1 + k * 128);
        unsigned long long bb0 = pack2(b0.x, b0.y);
        unsigned long long bb1 = pack2(b0.z, b0.w);
        unsigned long long bb2 = pack2(b1.x, b1.y);
        unsigned long long bb3 = pack2(b1.z, b1.w);
        float am[8] = {a0.x, a0.y, a0.z, a0.w, a1.x, a1.y, a1.z, a1.w};
#pragma unroll
        for (int i = 0; i < 8; i++) {
            unsigned long long aa = pack2(am[i], am[i]);
            fma2(acc[i][0], aa, bb0);
            fma2(acc[i][1], aa, bb1);
            fma2(acc[i][2], aa, bb2);
            fma2(acc[i][3], aa, bb3);
        }
    }

#pragma unroll
    for (int i = 0; i < 8; i++) {
        int node = e0 + ty * 8 + i;
        if (node < N) {
            float2 v0 = unpack2(acc[i][0]);
            float2 v1 = unpack2(acc[i][1]);
            float2 v2 = unpack2(acc[i][2]);
            float2 v3 = unpack2(acc[i][3]);
            __half2 h0 = __float22half2_rn(v0);
            __half2 h1 = __float22half2_rn(v1);
            __half2 h2 = __float22half2_rn(v2);
            __half2 h3 = __float22half2_rn(v3);
            __half* yrow = g_y + (long)node * YPITCH;
            *(uint2*)(yrow + tx * 4)      = make_uint2(*(uint32_t*)&h0, *(uint32_t*)&h1);
            *(uint2*)(yrow + 64 + tx * 4) = make_uint2(*(uint32_t*)&h2, *(uint32_t*)&h3);
        }
    }
}

// ============================================================================
// Kernel B: persistent fp16 mma.sync edge GEMM, 512 threads (R16 base).
// 16 warps = 4 rowgroups (32 edges) x 4 col-groups (32 cols), tile = 128.
// Y fp16 (L2-resident), combine in HALF2 (7 instrs/chunk), W2 register-
// resident. Gather in 4 uint4 chunks: chunk 0 LDG hoisted to prologue,
// chunks 1-3 at steps 2/4/6; converts at steps 4/6/tail/tail.
// ============================================================================
#define PITCH 272
#define TILE_M 128
#define OFF_W2   0
#define OFF_H    34816
#define RGBYTES  8704             /* 32 rows * 272 */
#define HBUF     34816            /* 4 rowgroups */
#define OFF_B1   (34816 + 2*34816)           /* 104448: b1 fp16[128] */
#define OFF_B2   (OFF_B1 + 256)
#define SMEM_EDGE (OFF_B2 + 512 + 1024)

__global__ void __launch_bounds__(512, 1) edge_mma(const int* __restrict__ ei,
                                                   const float* __restrict__ b1,
                                                   const float* __restrict__ W2,
                                                   const float* __restrict__ b2,
                                                   const float* __restrict__ epsp,
                                                   float* __restrict__ out,
                                                   int E, int N, int T) {
    extern __shared__ char smraw[];
    char* sm = (char*)(((uintptr_t)smraw + 1023) & ~(uintptr_t)1023);
    uint32_t sb = smem_u32(sm);

    __half* b1h = (__half*)(sm + OFF_B1);
    float*  b2s = (float*)(sm + OFF_B2);

    int tid = threadIdx.x, wid = tid >> 5, lane = tid & 31;
    int rg = wid >> 2, ch = wid & 3;
    int barid = rg + 1;

    // ---- one-time: W2 -> fp16, [n][k] padded rows; biases (b1 fp16) ----
    if (tid < 128) {
        b1h[tid] = (tid < OUT_CH) ? __float2half(b1[tid]) : __float2half(0.f);
        b2s[tid] = (tid < OUT_CH) ? b2[tid] : 0.f;
    }
    for (int i = tid; i < 128 * 128; i += 512) {
        int n = i >> 7, k = i & 127;
        float v = (n < OUT_CH && k < OUT_CH) ? W2[k * OUT_CH + n] : 0.f;
        *(__half*)(sm + OFF_W2 + n * PITCH + k * 2) = __float2half(v);
    }
    __syncthreads();

    // ---- preload this warp's B fragments (cols ch*32..+31, all K): 64 regs ----
    uint32_t b_off = (uint32_t)((8 * ((lane >> 4) & 1) + (lane & 7)) * PITCH + ((lane >> 3) & 1) * 16);
    uint32_t bfr[8][8];
    {
        uint32_t base = sb + OFF_W2 + (uint32_t)(ch * 32) * PITCH + b_off;
#pragma unroll
        for (int ks = 0; ks < 8; ks++) {
            uint32_t koff = (uint32_t)ks * 32u;
            LDSM_X4(bfr[ks][0], bfr[ks][1], bfr[ks][2], bfr[ks][3], base + koff);
            LDSM_X4(bfr[ks][4], bfr[ks][5], bfr[ks][6], bfr[ks][7], base + 16u * PITCH + koff);
        }
    }

    __half2 coef2 = __float2half2_rn(1.f + epsp[0]);
    __half2 zero2 = __float2half2_rn(0.f);
    int bid = blockIdx.x, G = gridDim.x;
    int nt_mine = (bid < T) ? (T - bid + G - 1) / G : 0;

    int m_local = ch * 8 + (lane >> 2);
    int m_tile  = rg * 32 + m_local;
    int kq      = (lane & 3) * 8;          // 8-half (16B) sub-chunk
    char* Hrg_base = sm + OFF_H + rg * RGBYTES + m_local * PITCH;

    // half2 combine of 8 halves (one uint4): h = relu(coef*yr + yc + b1)
    auto convert8 = [&](uint4 a, uint4 b, int k, char* dh) {
        uint4 bb = *(const uint4*)(b1h + k);
        __half2 t0 = __hmax2(__hadd2(__hfma2(coef2, *(__half2*)&a.x, *(__half2*)&b.x), *(__half2*)&bb.x), zero2);
        __half2 t1 = __hmax2(__hadd2(__hfma2(coef2, *(__half2*)&a.y, *(__half2*)&b.y), *(__half2*)&bb.y), zero2);
        __half2 t2 = __hmax2(__hadd2(__hfma2(coef2, *(__half2*)&a.z, *(__half2*)&b.z), *(__half2*)&bb.z), zero2);
        __half2 t3 = __hmax2(__hadd2(__hfma2(coef2, *(__half2*)&a.w, *(__half2*)&b.w), *(__half2*)&bb.w), zero2);
        *(uint4*)(dh + k * 2) = make_uint4(*(uint32_t*)&t0, *(uint32_t*)&t1,
                                           *(uint32_t*)&t2, *(uint32_t*)&t3);
    };

    auto load_idx = [&](int tile, int &r, int &c) {
        int e = tile * TILE_M + m_tile;
        int rr = 0, cc = 0;
        if (tile < T && e < E) { rr = ei[e]; cc = ei[E + e]; }
        if (rr < 0) rr = 0; if (rr >= N) rr = N - 1;
        if (cc < 0) cc = 0; if (cc >= N) cc = N - 1;
        r = rr; c = cc;
    };

    auto gather_sync = [&](int tile, int buf) {
        int r, c;
        load_idx(tile, r, c);
        const __half* yr = g_y + (long)r * YPITCH;
        const __half* yc = g_y + (long)c * YPITCH;
        char* dh = Hrg_base + buf * HBUF;
#pragma unroll
        for (int cI = 0; cI < 4; cI++) {
            int k = cI * 32 + kq;
            convert8(*(const uint4*)(yr + k), *(const uint4*)(yc + k), k, dh);
        }
    };

    uint32_t a_off = (uint32_t)(((lane & 7) + 8 * ((lane >> 3) & 1)) * PITCH + ((lane >> 4) & 1) * 16);
    uint32_t aA_base = sb + OFF_H + (uint32_t)rg * (uint32_t)RGBYTES + a_off;

    int cq = (lane & 3) * 2;

    int rn = 0, cn = 0;   // indices for tile j+1
    if (nt_mine > 0) {
        gather_sync(bid, 0);
        load_idx(bid + G, rn, cn);
        BAR_RG(barid);
    }

    for (int j = 0; j < nt_mine; j++) {
        int cur = j & 1;
        int tile = bid + j * G;
        bool gon = (j + 1 < nt_mine);

        const __half* yr = g_y + (long)rn * YPITCH;
        const __half* yc = g_y + (long)cn * YPITCH;
        load_idx(tile + 2 * G, rn, cn);

        char* dh = Hrg_base + (1 - cur) * HBUF;

        uint4 ya[2], yb[2];   // 2 uint4 chunk slots

        // hoist chunk 0 LDG to prologue: ~6 MMA steps of cover
        if (gon) {
            ya[0] = *(const uint4*)(yr + kq);
            yb[0] = *(const uint4*)(yc + kq);
        }

        float acc[2][4][4];
#pragma unroll
        for (int mh = 0; mh < 2; mh++)
#pragma unroll
            for (int t = 0; t < 4; t++) {
                float2 bv = *(const float2*)(b2s + ch * 32 + t * 8 + cq);
                acc[mh][t][0] = bv.x; acc[mh][t][1] = bv.y;
                acc[mh][t][2] = bv.x; acc[mh][t][3] = bv.y;
            }
        uint32_t ah_b = aA_base + (uint32_t)cur * (uint32_t)HBUF;

#pragma unroll
        for (int s = 0; s < 8; s++) {
            if (gon) {
                if (s >= 4 && (s & 1) == 0) {
                    // convert chunk (s-4)/2 (>=4 MMA-steps of cover)
                    int cc = (s - 4) >> 1;
                    convert8(ya[cc & 1], yb[cc & 1], cc * 32 + kq, dh);
                }
                if ((s & 1) == 0 && s > 0) {
                    // load chunk s/2 into slot (s/2)&1 (freed by convert above)
                    int cc = s >> 1;
                    int k = cc * 32 + kq;
                    ya[cc & 1] = *(const uint4*)(yr + k);
                    yb[cc & 1] = *(const uint4*)(yc + k);
                }
            }
            // MMA step ks = s: A from smem, B from registers
            uint32_t koff = (uint32_t)s * 32u;
            uint32_t ah0[4], ah1[4];
            LDSM_X4(ah0[0], ah0[1], ah0[2], ah0[3], ah_b + koff);
            LDSM_X4(ah1[0], ah1[1], ah1[2], ah1[3], ah_b + 16u * PITCH + koff);
            const uint32_t* bk = bfr[s];
#pragma unroll
            for (int n8 = 0; n8 < 4; n8++)
                mma16816(acc[0][n8], ah0, bk[n8 * 2], bk[n8 * 2 + 1]);
#pragma unroll
            for (int n8 = 0; n8 < 4; n8++)
                mma16816(acc[1][n8], ah1, bk[n8 * 2], bk[n8 * 2 + 1]);
        }

        // tail: convert chunk 2 (loaded step 4), then epilogue, then chunk 3
        if (gon) convert8(ya[0], yb[0], 2 * 32 + kq, dh);

        // epilogue: streaming scalar stores (evict-first: keep Y in L2)
#pragma unroll
        for (int mh = 0; mh < 2; mh++) {
            int e0row = tile * TILE_M + rg * 32 + mh * 16 + (lane >> 2);
            int e1row = e0row + 8;
            bool v0 = e0row < E, v1 = e1row < E;
            float* o0 = out + (long)e0row * OUT_CH;
            float* o1 = out + (long)e1row * OUT_CH;
#pragma unroll
            for (int t = 0; t < 4; t++) {
                int n0 = ch * 32 + t * 8 + cq;
                if (n0 < OUT_CH) {
                    if (v0) __stcs(o0 + n0, acc[mh][t][0]);
                    if (v1) __stcs(o1 + n0, acc[mh][t][2]);
                    if (n0 + 1 < OUT_CH) {
                        if (v0) __stcs(o0 + n0 + 1, acc[mh][t][1]);
                        if (v1) __stcs(o1 + n0 + 1, acc[mh][t][3]);
                    }
                }
            }
        }

        if (gon) convert8(ya[1], yb[1], 3 * 32 + kq, dh);

        BAR_RG(barid);
    }
}

extern "C" void kernel_launch(void* const* d_in, const int* in_sizes, int n_in,
                              void* d_out, int out_size) {
    const float* x   = (const float*)d_in[0];
    const int*   ei  = (const int*)d_in[1];
    const float* W1  = (const float*)d_in[2];
    const float* b1  = (const float*)d_in[3];
    const float* W2  = (const float*)d_in[4];
    const float* b2  = (const float*)d_in[5];
    const float* eps = (const float*)d_in[6];
    float* out = (float*)d_out;

    int N = in_sizes[0] / IN_CH;
    int E = in_sizes[1] / 2;
    int T = (E + TILE_M - 1) / TILE_M;

    size_t smA = (size_t)(IN_CH * 132 + IN_CH * 128) * sizeof(float);
    cudaFuncSetAttribute(node_gemm, cudaFuncAttributeMaxDynamicSharedMemorySize, (int)smA);
    cudaFuncSetAttribute(edge_mma, cudaFuncAttributeMaxDynamicSharedMemorySize, SMEM_EDGE);

    node_gemm<<<(N + 127) / 128, 256, smA>>>(x, W1, N);

    int grid = 148; if (grid > T) grid = T;
    edge_mma<<<grid, 512, SMEM_EDGE>>>(ei, b1, W2, b2, eps, out, E, N, T);
}